// round 7
// baseline (speedup 1.0000x reference)
#include <cuda_runtime.h>
#include <cstdint>

// SSIM map, fused separable 11x11 gaussian, reflect padding.
// Sum/difference channel folding: p=a+b, q=a-b staged in smem; TWO packed
// f32x2 conv channels: (p,q) -> means, (p^2,q^2) -> moments.
//   mu1*mu2 = (mp^2-mq^2)/4   mu1^2+mu2^2 = (mp^2+mq^2)/2
//   S12     = (Tp-Tq)/4       S11+S22     = (Tp+Tq)/2
// cp.async double-buffered staging; 44-reg ring; 5 CTAs/SM.
// R7: 4-way split accumulator chains in both conv loops (latency, not
// throughput, was binding: 2 chains capped issue at ~50%).

#define HW   512
#define RAD  5
#define WIN  11
#define BW   128
#define BH   64
#define NT   128
#define RW   (BW + 2*RAD)   // 138
#define NGRP 7
#define NIT  (BH + 2*RAD)   // 74

typedef unsigned long long ull;

__device__ __forceinline__ int reflect_idx(int i) {
    if (i < 0) i = -i;
    if (i >= HW) i = 2 * HW - 2 - i;
    return i;
}

__device__ __forceinline__ ull pack2(float x, float y) {
    ull r; asm("mov.b64 %0, {%1, %2};" : "=l"(r) : "f"(x), "f"(y)); return r;
}
__device__ __forceinline__ float2 unpack2(ull v) {
    float2 r; asm("mov.b64 {%0, %1}, %2;" : "=f"(r.x), "=f"(r.y) : "l"(v)); return r;
}
__device__ __forceinline__ ull fma2(ull a, ull b, ull c) {
    ull d; asm("fma.rn.f32x2 %0, %1, %2, %3;" : "=l"(d) : "l"(a), "l"(b), "l"(c)); return d;
}
__device__ __forceinline__ ull mul2(ull a, ull b) {
    ull d; asm("mul.rn.f32x2 %0, %1, %2;" : "=l"(d) : "l"(a), "l"(b)); return d;
}
__device__ __forceinline__ ull add2(ull a, ull b) {
    ull d; asm("add.rn.f32x2 %0, %1, %2;" : "=l"(d) : "l"(a), "l"(b)); return d;
}

__device__ __forceinline__ void cp4(uint32_t dst, const float* src) {
    asm volatile("cp.async.ca.shared.global [%0], [%1], 4;" :: "r"(dst), "l"(src));
}
__device__ __forceinline__ void cp_commit() {
    asm volatile("cp.async.commit_group;");
}
__device__ __forceinline__ void cp_wait_all() {
    asm volatile("cp.async.wait_group 0;");
}

#define W0 0.00102838f
#define W1 0.00759876f
#define W2 0.03600078f
#define W3 0.10936069f
#define W4 0.21300554f
#define W5 0.26601173f

__global__ __launch_bounds__(NT, 5)
void ssim_kernel(const float* __restrict__ img1,
                 const float* __restrict__ img2,
                 float* __restrict__ out) {
    __shared__ float2 sRow[2][WIN][RW];

    const int tid = threadIdx.x;
    const int X0 = blockIdx.x * BW;
    const int Y0 = blockIdx.y * BH;
    const int img = blockIdx.z;
    const float* __restrict__ A = img1 + (size_t)img * HW * HW;
    const float* __restrict__ B = img2 + (size_t)img * HW * HW;
    float* __restrict__ O = out + (size_t)img * HW * HW;

    const ull WP[WIN] = {pack2(W0,W0), pack2(W1,W1), pack2(W2,W2), pack2(W3,W3),
                         pack2(W4,W4), pack2(W5,W5), pack2(W4,W4), pack2(W3,W3),
                         pack2(W2,W2), pack2(W1,W1), pack2(W0,W0)};

    const int gx0 = reflect_idx(X0 - RAD + tid);
    const int gx1 = reflect_idx(X0 - RAD + tid + NT);
    const bool has2 = (tid < RW - NT);

    const uint32_t sbase = (uint32_t)__cvta_generic_to_shared(&sRow[0][0][0]);

    auto stage = [&](int g, int buf) {
        const int by = Y0 - RAD + g * WIN;
        const uint32_t b0 = sbase + (uint32_t)(buf * WIN * RW) * 8u + (uint32_t)tid * 8u;
        #pragma unroll
        for (int r = 0; r < WIN; r++) {
            int gy = reflect_idx(by + r);
            const float* Ar = A + gy * HW;
            const float* Br = B + gy * HW;
            uint32_t d0 = b0 + (uint32_t)(r * RW) * 8u;
            cp4(d0,     Ar + gx0);
            cp4(d0 + 4, Br + gx0);
            if (has2) {
                uint32_t d1 = d0 + (uint32_t)NT * 8u;
                cp4(d1,     Ar + gx1);
                cp4(d1 + 4, Br + gx1);
            }
        }
        cp_commit();
    };

    ull rm[WIN], rw[WIN];

    stage(0, 0);

    for (int grp = 0; grp < NGRP; grp++) {
        cp_wait_all();
        __syncthreads();

        if (grp + 1 < NGRP) stage(grp + 1, (grp + 1) & 1);

        const int buf = grp & 1;

        // ---- in-place transform (a,b) -> (p,q), once per staged pixel ----
        #pragma unroll
        for (int r = 0; r < WIN; r++) {
            float2 v = sRow[buf][r][tid];
            sRow[buf][r][tid] = make_float2(v.x + v.y, v.x - v.y);
            if (has2) {
                float2 u = sRow[buf][r][tid + NT];
                sRow[buf][r][tid + NT] = make_float2(u.x + u.y, u.x - u.y);
            }
        }
        __syncthreads();

        #pragma unroll
        for (int p = 0; p < WIN; p++) {
            int it = grp * WIN + p;
            if (it >= NIT) break;

            // ---- horizontal 11-tap conv, 4 split accumulator chains ----
            ull am0 = 0ull, am1 = 0ull, aw0 = 0ull, aw1 = 0ull;
            #pragma unroll
            for (int j = 0; j < WIN; j++) {
                float2 v = sRow[buf][p][tid + j];     // LDS.64: (p,q)
                ull pv  = pack2(v.x, v.y);
                ull pv2 = mul2(pv, pv);               // (p^2, q^2)
                if (j & 1) {
                    am1 = fma2(pv,  WP[j], am1);
                    aw1 = fma2(pv2, WP[j], aw1);
                } else {
                    am0 = fma2(pv,  WP[j], am0);
                    aw0 = fma2(pv2, WP[j], aw0);
                }
            }
            rm[p] = add2(am0, am1);
            rw[p] = add2(aw0, aw1);

            if (it >= 2 * RAD) {
                // ---- vertical 11-tap conv, 4 split chains + pointwise ----
                ull vm0 = 0ull, vm1 = 0ull, vw0 = 0ull, vw1 = 0ull;
                #pragma unroll
                for (int q = 0; q < WIN; q++) {
                    const int jj = 10 - ((p - q + WIN) % WIN);  // compile-time
                    if (q & 1) {
                        vm1 = fma2(rm[q], WP[jj], vm1);
                        vw1 = fma2(rw[q], WP[jj], vw1);
                    } else {
                        vm0 = fma2(rm[q], WP[jj], vm0);
                        vw0 = fma2(rw[q], WP[jj], vw0);
                    }
                }
                ull vm = add2(vm0, vm1);
                ull vw = add2(vw0, vw1);
                float2 m2 = unpack2(mul2(vm, vm));  // (mp^2, mq^2)
                float2 t  = unpack2(vw);            // (Tp, Tq)
                float mu12 = 0.25f * (m2.x - m2.y);
                float musq = 0.50f * (m2.x + m2.y);
                float s12  = 0.25f * (t.x - t.y) - mu12;
                float ssum = 0.50f * (t.x + t.y) - musq;
                const float C1 = 1e-4f;
                const float C2 = 9e-4f;
                float num = (2.f * mu12 + C1) * (2.f * s12 + C2);
                float den = (musq + C1) * (ssum + C2);
                O[(Y0 + it - 2 * RAD) * HW + X0 + tid] = __fdividef(num, den);
            }
        }
    }
}

extern "C" void kernel_launch(void* const* d_in, const int* in_sizes, int n_in,
                              void* d_out, int out_size) {
    const float* img1 = (const float*)d_in[0];
    const float* img2 = (const float*)d_in[1];
    // d_in[2]: gaussian window — fixed (11, 1.5), baked in as immediates.
    float* out = (float*)d_out;

    dim3 grid(HW / BW, HW / BH, 48);   // 4 x 8 x 48 = 1536 blocks
    dim3 block(NT);
    ssim_kernel<<<grid, block>>>(img1, img2, out);
}

// round 8
// speedup vs baseline: 1.3022x; 1.3022x over previous
#include <cuda_runtime.h>
#include <cstdint>

// SSIM map, fused separable 11x11 gaussian, reflect padding.
// Channels: (a,b) raw -> conv gives (mu1,mu2) directly.
//           (p^2,q^2) with p=a+b,q=a-b -> conv gives (Tp,Tq):
//             S11+S22 = (Tp+Tq)/2,  S12 = (Tp-Tq)/4.
// Squares precomputed ONCE per staged pixel (kills the per-tap mul2).
// cp.async double-buffered raw staging; single-buffered squares array.
// 44-reg ring; 5 CTAs/SM. (R7's split-accumulator experiment reverted.)

#define HW   512
#define RAD  5
#define WIN  11
#define BW   128
#define BH   64
#define NT   128
#define RW   (BW + 2*RAD)   // 138
#define NGRP 7
#define NIT  (BH + 2*RAD)   // 74

typedef unsigned long long ull;

__device__ __forceinline__ int reflect_idx(int i) {
    if (i < 0) i = -i;
    if (i >= HW) i = 2 * HW - 2 - i;
    return i;
}

__device__ __forceinline__ ull pack2(float x, float y) {
    ull r; asm("mov.b64 %0, {%1, %2};" : "=l"(r) : "f"(x), "f"(y)); return r;
}
__device__ __forceinline__ float2 unpack2(ull v) {
    float2 r; asm("mov.b64 {%0, %1}, %2;" : "=f"(r.x), "=f"(r.y) : "l"(v)); return r;
}
__device__ __forceinline__ ull fma2(ull a, ull b, ull c) {
    ull d; asm("fma.rn.f32x2 %0, %1, %2, %3;" : "=l"(d) : "l"(a), "l"(b), "l"(c)); return d;
}
__device__ __forceinline__ ull mul2(ull a, ull b) {
    ull d; asm("mul.rn.f32x2 %0, %1, %2;" : "=l"(d) : "l"(a), "l"(b)); return d;
}

__device__ __forceinline__ void cp4(uint32_t dst, const float* src) {
    asm volatile("cp.async.ca.shared.global [%0], [%1], 4;" :: "r"(dst), "l"(src));
}
__device__ __forceinline__ void cp_commit() {
    asm volatile("cp.async.commit_group;");
}
__device__ __forceinline__ void cp_wait_all() {
    asm volatile("cp.async.wait_group 0;");
}

#define W0 0.00102838f
#define W1 0.00759876f
#define W2 0.03600078f
#define W3 0.10936069f
#define W4 0.21300554f
#define W5 0.26601173f

__global__ __launch_bounds__(NT, 5)
void ssim_kernel(const float* __restrict__ img1,
                 const float* __restrict__ img2,
                 float* __restrict__ out) {
    __shared__ float2 sRaw[2][WIN][RW];   // (a,b), double-buffered (cp.async)
    __shared__ float2 sSQ[WIN][RW];       // (p^2,q^2), single-buffered

    const int tid = threadIdx.x;
    const int X0 = blockIdx.x * BW;
    const int Y0 = blockIdx.y * BH;
    const int img = blockIdx.z;
    const float* __restrict__ A = img1 + (size_t)img * HW * HW;
    const float* __restrict__ B = img2 + (size_t)img * HW * HW;
    float* __restrict__ O = out + (size_t)img * HW * HW;

    const ull WP[WIN] = {pack2(W0,W0), pack2(W1,W1), pack2(W2,W2), pack2(W3,W3),
                         pack2(W4,W4), pack2(W5,W5), pack2(W4,W4), pack2(W3,W3),
                         pack2(W2,W2), pack2(W1,W1), pack2(W0,W0)};

    const int gx0 = reflect_idx(X0 - RAD + tid);
    const int gx1 = reflect_idx(X0 - RAD + tid + NT);
    const bool has2 = (tid < RW - NT);    // 10 threads stage a second column

    const uint32_t sbase = (uint32_t)__cvta_generic_to_shared(&sRaw[0][0][0]);

    auto stage = [&](int g, int buf) {
        const int by = Y0 - RAD + g * WIN;
        const uint32_t b0 = sbase + (uint32_t)(buf * WIN * RW) * 8u + (uint32_t)tid * 8u;
        #pragma unroll
        for (int r = 0; r < WIN; r++) {
            int gy = reflect_idx(by + r);
            const float* Ar = A + gy * HW;
            const float* Br = B + gy * HW;
            uint32_t d0 = b0 + (uint32_t)(r * RW) * 8u;
            cp4(d0,     Ar + gx0);
            cp4(d0 + 4, Br + gx0);
            if (has2) {
                uint32_t d1 = d0 + (uint32_t)NT * 8u;
                cp4(d1,     Ar + gx1);
                cp4(d1 + 4, Br + gx1);
            }
        }
        cp_commit();
    };

    // register ring: packed (mu1,mu2) partials and (Tp,Tq) partials per row
    ull rm[WIN], rw[WIN];

    stage(0, 0);

    for (int grp = 0; grp < NGRP; grp++) {
        cp_wait_all();     // this group's raw rows landed
        __syncthreads();   // prior group's compute (readers of sSQ/sRaw) done

        if (grp + 1 < NGRP) stage(grp + 1, (grp + 1) & 1);

        const int buf = grp & 1;

        // ---- per-pixel squares: (a,b) -> (p^2,q^2), once per staged pixel ----
        #pragma unroll
        for (int r = 0; r < WIN; r++) {
            float2 v = sRaw[buf][r][tid];
            float p = v.x + v.y, q = v.x - v.y;
            sSQ[r][tid] = unpack2(mul2(pack2(p, q), pack2(p, q)));
            if (has2) {
                float2 u = sRaw[buf][r][tid + NT];
                float p2 = u.x + u.y, q2 = u.x - u.y;
                sSQ[r][tid + NT] = unpack2(mul2(pack2(p2, q2), pack2(p2, q2)));
            }
        }
        __syncthreads();

        #pragma unroll
        for (int p = 0; p < WIN; p++) {
            int it = grp * WIN + p;
            if (it >= NIT) break;

            // ---- horizontal 11-tap conv: 2 packed channels, no per-tap mul ----
            ull am = 0ull, aw = 0ull;
            #pragma unroll
            for (int j = 0; j < WIN; j++) {
                float2 v = sRaw[buf][p][tid + j];   // LDS.64: (a,b)
                float2 s = sSQ[p][tid + j];         // LDS.64: (p^2,q^2)
                am = fma2(pack2(v.x, v.y), WP[j], am);
                aw = fma2(pack2(s.x, s.y), WP[j], aw);
            }
            rm[p] = am; rw[p] = aw;

            if (it >= 2 * RAD) {
                // ---- vertical 11-tap conv over ring + SSIM pointwise ----
                ull vm = 0ull, vw = 0ull;
                #pragma unroll
                for (int q = 0; q < WIN; q++) {
                    const int jj = 10 - ((p - q + WIN) % WIN);  // compile-time
                    vm = fma2(rm[q], WP[jj], vm);
                    vw = fma2(rw[q], WP[jj], vw);
                }
                float2 m = unpack2(vm);             // (mu1, mu2)
                float2 t = unpack2(vw);             // (Tp, Tq)
                float mu12 = m.x * m.y;
                float musq = fmaf(m.x, m.x, m.y * m.y);
                float s12  = 0.25f * (t.x - t.y) - mu12;   // sigma12
                float ssum = 0.50f * (t.x + t.y) - musq;   // sigma1+sigma2
                const float C1 = 1e-4f;
                const float C2 = 9e-4f;
                float num = (2.f * mu12 + C1) * (2.f * s12 + C2);
                float den = (musq + C1) * (ssum + C2);
                O[(Y0 + it - 2 * RAD) * HW + X0 + tid] = __fdividef(num, den);
            }
        }
    }
}

extern "C" void kernel_launch(void* const* d_in, const int* in_sizes, int n_in,
                              void* d_out, int out_size) {
    const float* img1 = (const float*)d_in[0];
    const float* img2 = (const float*)d_in[1];
    // d_in[2]: gaussian window — fixed (11, 1.5), baked in as immediates.
    float* out = (float*)d_out;

    dim3 grid(HW / BW, HW / BH, 48);   // 4 x 8 x 48 = 1536 blocks
    dim3 block(NT);
    ssim_kernel<<<grid, block>>>(img1, img2, out);
}

// round 10
// speedup vs baseline: 1.6560x; 1.2716x over previous
#include <cuda_runtime.h>
#include <cstdint>

// SSIM map, fused separable 11x11 gaussian, reflect padding.
// (Resubmission of R9 — previous bench died to a broker/container failure,
//  not a kernel error.)
// R6 structure (proven local optimum for the inner loop):
//   stage raw (a,b) -> in-place transform to (p,q)=(a+b,a-b);
//   TWO packed f32x2 conv channels: (p,q) means, per-tap mul2 squares.
//   mu1*mu2 = (mp^2-mq^2)/4   mu1^2+mu2^2 = (mp^2+mq^2)/2
//   S12     = (Tp-Tq)/4       S11+S22     = (Tp+Tq)/2
// R9 change: NT=64 (2-warp CTAs), 10 CTAs/SM — cheap barriers, many
// independent warps per SMSP to cover LDS->fma latency.

#define HW   512
#define RAD  5
#define WIN  11
#define BW   64             // output columns per block (= threads)
#define BH   64             // output rows per block
#define NT   64
#define RW   (BW + 2*RAD)   // 74
#define NGRP 7              // 7*11 = 77 >= BH + 2*RAD
#define NIT  (BH + 2*RAD)   // 74

typedef unsigned long long ull;

__device__ __forceinline__ int reflect_idx(int i) {
    if (i < 0) i = -i;
    if (i >= HW) i = 2 * HW - 2 - i;
    return i;
}

__device__ __forceinline__ ull pack2(float x, float y) {
    ull r; asm("mov.b64 %0, {%1, %2};" : "=l"(r) : "f"(x), "f"(y)); return r;
}
__device__ __forceinline__ float2 unpack2(ull v) {
    float2 r; asm("mov.b64 {%0, %1}, %2;" : "=f"(r.x), "=f"(r.y) : "l"(v)); return r;
}
__device__ __forceinline__ ull fma2(ull a, ull b, ull c) {
    ull d; asm("fma.rn.f32x2 %0, %1, %2, %3;" : "=l"(d) : "l"(a), "l"(b), "l"(c)); return d;
}
__device__ __forceinline__ ull mul2(ull a, ull b) {
    ull d; asm("mul.rn.f32x2 %0, %1, %2;" : "=l"(d) : "l"(a), "l"(b)); return d;
}

__device__ __forceinline__ void cp4(uint32_t dst, const float* src) {
    asm volatile("cp.async.ca.shared.global [%0], [%1], 4;" :: "r"(dst), "l"(src));
}
__device__ __forceinline__ void cp_commit() {
    asm volatile("cp.async.commit_group;");
}
__device__ __forceinline__ void cp_wait_all() {
    asm volatile("cp.async.wait_group 0;");
}

#define W0 0.00102838f
#define W1 0.00759876f
#define W2 0.03600078f
#define W3 0.10936069f
#define W4 0.21300554f
#define W5 0.26601173f

__global__ __launch_bounds__(NT, 10)
void ssim_kernel(const float* __restrict__ img1,
                 const float* __restrict__ img2,
                 float* __restrict__ out) {
    __shared__ float2 sRow[2][WIN][RW];   // 2 x 11 x 74 x 8B = 12.7 KB

    const int tid = threadIdx.x;
    const int X0 = blockIdx.x * BW;
    const int Y0 = blockIdx.y * BH;
    const int img = blockIdx.z;
    const float* __restrict__ A = img1 + (size_t)img * HW * HW;
    const float* __restrict__ B = img2 + (size_t)img * HW * HW;
    float* __restrict__ O = out + (size_t)img * HW * HW;

    const ull WP[WIN] = {pack2(W0,W0), pack2(W1,W1), pack2(W2,W2), pack2(W3,W3),
                         pack2(W4,W4), pack2(W5,W5), pack2(W4,W4), pack2(W3,W3),
                         pack2(W2,W2), pack2(W1,W1), pack2(W0,W0)};

    // loop-invariant column reflects
    const int gx0 = reflect_idx(X0 - RAD + tid);
    const int gx1 = reflect_idx(X0 - RAD + tid + NT);
    const bool has2 = (tid < RW - NT);     // 10 threads stage a second column

    const uint32_t sbase = (uint32_t)__cvta_generic_to_shared(&sRow[0][0][0]);

    auto stage = [&](int g, int buf) {
        const int by = Y0 - RAD + g * WIN;
        const uint32_t b0 = sbase + (uint32_t)(buf * WIN * RW) * 8u + (uint32_t)tid * 8u;
        #pragma unroll
        for (int r = 0; r < WIN; r++) {
            int gy = reflect_idx(by + r);
            const float* Ar = A + gy * HW;
            const float* Br = B + gy * HW;
            uint32_t d0 = b0 + (uint32_t)(r * RW) * 8u;
            cp4(d0,     Ar + gx0);
            cp4(d0 + 4, Br + gx0);
            if (has2) {
                uint32_t d1 = d0 + (uint32_t)NT * 8u;
                cp4(d1,     Ar + gx1);
                cp4(d1 + 4, Br + gx1);
            }
        }
        cp_commit();
    };

    // register ring: packed (sp,sq) means and (sp2,sq2) moments per row
    ull rm[WIN], rw[WIN];

    stage(0, 0);   // prologue prefetch

    for (int grp = 0; grp < NGRP; grp++) {
        cp_wait_all();     // this group's rows landed
        __syncthreads();   // visible to all; prior readers done

        if (grp + 1 < NGRP) stage(grp + 1, (grp + 1) & 1);

        const int buf = grp & 1;

        // ---- in-place transform (a,b) -> (p,q) = (a+b, a-b), once/pixel ----
        #pragma unroll
        for (int r = 0; r < WIN; r++) {
            float2 v = sRow[buf][r][tid];
            sRow[buf][r][tid] = make_float2(v.x + v.y, v.x - v.y);
            if (has2) {
                float2 u = sRow[buf][r][tid + NT];
                sRow[buf][r][tid + NT] = make_float2(u.x + u.y, u.x - u.y);
            }
        }
        __syncthreads();

        #pragma unroll
        for (int p = 0; p < WIN; p++) {
            int it = grp * WIN + p;
            if (it >= NIT) break;    // uniform tail skip (last group)

            // ---- horizontal 11-tap conv: 2 packed channels ----
            ull am = 0ull, aw = 0ull;
            #pragma unroll
            for (int j = 0; j < WIN; j++) {
                float2 v = sRow[buf][p][tid + j];     // LDS.64: (p,q)
                ull pv  = pack2(v.x, v.y);
                ull pv2 = mul2(pv, pv);               // (p^2, q^2)
                am = fma2(pv,  WP[j], am);
                aw = fma2(pv2, WP[j], aw);
            }
            rm[p] = am; rw[p] = aw;

            if (it >= 2 * RAD) {
                // ---- vertical 11-tap conv over ring + SSIM pointwise ----
                ull vm = 0ull, vw = 0ull;
                #pragma unroll
                for (int q = 0; q < WIN; q++) {
                    const int jj = 10 - ((p - q + WIN) % WIN);  // compile-time
                    vm = fma2(rm[q], WP[jj], vm);
                    vw = fma2(rw[q], WP[jj], vw);
                }
                float2 m2 = unpack2(mul2(vm, vm));  // (mp^2, mq^2)
                float2 t  = unpack2(vw);            // (Tp, Tq)
                float mu12 = 0.25f * (m2.x - m2.y);        // mu1*mu2
                float musq = 0.50f * (m2.x + m2.y);        // mu1^2+mu2^2
                float s12  = 0.25f * (t.x - t.y) - mu12;   // sigma12
                float ssum = 0.50f * (t.x + t.y) - musq;   // sigma1+sigma2
                const float C1 = 1e-4f;
                const float C2 = 9e-4f;
                float num = (2.f * mu12 + C1) * (2.f * s12 + C2);
                float den = (musq + C1) * (ssum + C2);
                O[(Y0 + it - 2 * RAD) * HW + X0 + tid] = __fdividef(num, den);
            }
        }
    }
}

extern "C" void kernel_launch(void* const* d_in, const int* in_sizes, int n_in,
                              void* d_out, int out_size) {
    const float* img1 = (const float*)d_in[0];
    const float* img2 = (const float*)d_in[1];
    // d_in[2]: gaussian window — fixed (11, 1.5), baked in as immediates.
    float* out = (float*)d_out;

    dim3 grid(HW / BW, HW / BH, 48);   // 8 x 8 x 48 = 3072 blocks
    dim3 block(NT);
    ssim_kernel<<<grid, block>>>(img1, img2, out);
}